// round 1
// baseline (speedup 1.0000x reference)
#include <cuda_runtime.h>
#include <math.h>
#include <stdint.h>

#define BATCH 2
#define LQ 13294
#define LEN_IN 13294
#define DM 256
#define NH 8
#define HD 32
#define MROWS (BATCH * LQ)   // 26588

// ---------------- scratch (device globals; no allocations allowed) ----------
__device__ float g_value[(size_t)BATCH * LEN_IN * DM];   // [B, LEN_IN, NH, HD]
__device__ float g_offs[(size_t)BATCH * LQ * DM];        // [B, LQ, NH, 16, 2]
__device__ float g_logits[(size_t)BATCH * LQ * NH * 16]; // [B, LQ, NH, 16]
__device__ float g_acc[(size_t)BATCH * LQ * DM];         // [B, LQ, NH, HD]

// ---------------- SGEMM: C[M,N] = A[M,K] @ B[K,N] + bias[N] -----------------
// BM=128, BN=64, BK=16, TM=8, TN=4, 256 threads.
__global__ __launch_bounds__(256) void sgemm_bias_kernel(
    const float* __restrict__ A, const float* __restrict__ B,
    const float* __restrict__ bias, float* __restrict__ C,
    int M, int N, int K)
{
    constexpr int BM = 128, BN = 64, BK = 16, TM = 8, TN = 4;
    __shared__ __align__(16) float As[BK][BM];
    __shared__ __align__(16) float Bs[BK][BN];

    const int tid = threadIdx.x;
    const int tx = tid & 15;   // N direction (16 * TN = 64)
    const int ty = tid >> 4;   // M direction (16 * TM = 128)
    const int bm = blockIdx.y * BM;
    const int bn = blockIdx.x * BN;

    // A tile: 128x16 floats = 512 float4, 2 per thread
    const int arow  = tid >> 2;        // 0..63
    const int acol4 = (tid & 3) * 4;   // 0,4,8,12
    // B tile: 16x64 floats = 256 float4, 1 per thread
    const int brow = tid >> 4;         // 0..15
    const int bcol = (tid & 15) * 4;

    float acc[TM][TN] = {};

    for (int k0 = 0; k0 < K; k0 += BK) {
        #pragma unroll
        for (int r = 0; r < 2; ++r) {
            const int row = bm + arow + r * 64;
            float4 v = make_float4(0.f, 0.f, 0.f, 0.f);
            if (row < M)
                v = *reinterpret_cast<const float4*>(A + (size_t)row * K + k0 + acol4);
            As[acol4 + 0][arow + r * 64] = v.x;
            As[acol4 + 1][arow + r * 64] = v.y;
            As[acol4 + 2][arow + r * 64] = v.z;
            As[acol4 + 3][arow + r * 64] = v.w;
        }
        *reinterpret_cast<float4*>(&Bs[brow][bcol]) =
            *reinterpret_cast<const float4*>(B + (size_t)(k0 + brow) * N + bn + bcol);
        __syncthreads();

        #pragma unroll
        for (int k = 0; k < BK; ++k) {
            float4 a0 = *reinterpret_cast<const float4*>(&As[k][ty * TM]);
            float4 a1 = *reinterpret_cast<const float4*>(&As[k][ty * TM + 4]);
            float4 b0 = *reinterpret_cast<const float4*>(&Bs[k][tx * TN]);
            float ra[TM] = {a0.x, a0.y, a0.z, a0.w, a1.x, a1.y, a1.z, a1.w};
            float rb[TN] = {b0.x, b0.y, b0.z, b0.w};
            #pragma unroll
            for (int i = 0; i < TM; ++i)
                #pragma unroll
                for (int j = 0; j < TN; ++j)
                    acc[i][j] += ra[i] * rb[j];
        }
        __syncthreads();
    }

    #pragma unroll
    for (int i = 0; i < TM; ++i) {
        const int row = bm + ty * TM + i;
        if (row >= M) continue;
        #pragma unroll
        for (int j = 0; j < TN; ++j) {
            const int col = bn + tx * TN + j;
            C[(size_t)row * N + col] = acc[i][j] + bias[col];
        }
    }
}

// ---------------- sampling + fused 16-way softmax ---------------------------
// One block per (b,q); one warp per head; lane = head-dim channel.
__global__ __launch_bounds__(256) void sample_kernel(
    const float* __restrict__ refp)   // [B, LQ, 4, 2]
{
    const int LH[4] = {100, 50, 25, 13};
    const int LW[4] = {100, 50, 25, 13};
    const int LS[4] = {0, 10000, 12500, 13125};

    const int bq = blockIdx.x;              // 0 .. B*LQ-1
    const int b  = bq / LQ;
    const int h  = threadIdx.x >> 5;
    const int lane = threadIdx.x & 31;

    // ---- softmax over the 16 (level,point) logits (lanes 0..15 hold them) ----
    float logit = -INFINITY;
    if (lane < 16) logit = g_logits[((size_t)bq * NH + h) * 16 + lane];
    float m = logit;
    #pragma unroll
    for (int o = 16; o > 0; o >>= 1) m = fmaxf(m, __shfl_xor_sync(0xffffffffu, m, o));
    float e = (lane < 16) ? __expf(logit - m) : 0.f;
    float s = e;
    #pragma unroll
    for (int o = 16; o > 0; o >>= 1) s += __shfl_xor_sync(0xffffffffu, s, o);
    const float wt = e / s;

    // ---- per-lane (i = l*4+p) sample location ----
    int ix0 = 0, iy0 = 0;
    float tx = 0.f, ty = 0.f;
    if (lane < 16) {
        const int l = lane >> 2;
        const float lw = (float)LW[l], lh = (float)LH[l];
        const float* op = g_offs + (((size_t)bq * NH + h) * 16 + lane) * 2;
        const float ox = op[0], oy = op[1];
        const float* rp = refp + ((size_t)bq * 4 + l) * 2;
        const float locx = rp[0] + ox / lw;
        const float locy = rp[1] + oy / lh;
        const float x = locx * lw - 0.5f;
        const float y = locy * lh - 0.5f;
        const float fx = floorf(x), fy = floorf(y);
        tx = x - fx; ty = y - fy;
        ix0 = (int)fx; iy0 = (int)fy;
    }

    float acc = 0.f;
    #pragma unroll
    for (int i = 0; i < 16; ++i) {
        const int l  = i >> 2;
        const int w  = LW[l], hh = LH[l], s0 = LS[l];
        const int   jx  = __shfl_sync(0xffffffffu, ix0, i);
        const int   jy  = __shfl_sync(0xffffffffu, iy0, i);
        const float ftx = __shfl_sync(0xffffffffu, tx, i);
        const float fty = __shfl_sync(0xffffffffu, ty, i);
        const float fw  = __shfl_sync(0xffffffffu, wt, i);

        const float* base = g_value + (((size_t)b * LEN_IN + s0) * NH + h) * HD + lane;
        const bool xv0 = (jx >= 0)     && (jx < w);
        const bool xv1 = (jx + 1 >= 0) && (jx + 1 < w);
        const bool yv0 = (jy >= 0)     && (jy < hh);
        const bool yv1 = (jy + 1 >= 0) && (jy + 1 < hh);

        float v00 = 0.f, v01 = 0.f, v10 = 0.f, v11 = 0.f;
        if (xv0 && yv0) v00 = base[(size_t)(jy * w + jx) * DM];
        if (xv1 && yv0) v01 = base[(size_t)(jy * w + jx + 1) * DM];
        if (xv0 && yv1) v10 = base[(size_t)((jy + 1) * w + jx) * DM];
        if (xv1 && yv1) v11 = base[(size_t)((jy + 1) * w + jx + 1) * DM];

        const float samp = v00 * (1.f - ftx) * (1.f - fty)
                         + v01 * ftx         * (1.f - fty)
                         + v10 * (1.f - ftx) * fty
                         + v11 * ftx         * fty;
        acc += fw * samp;
    }
    g_acc[(size_t)bq * DM + h * HD + lane] = acc;
}

// ---------------- launch ----------------------------------------------------
extern "C" void kernel_launch(void* const* d_in, const int* in_sizes, int n_in,
                              void* d_out, int out_size)
{
    const float* query  = (const float*)d_in[0];
    const float* refp   = (const float*)d_in[1];
    const float* inputf = (const float*)d_in[2];
    // d_in[3] = input_spatial_shapes (compile-time constants)
    const float* Wv   = (const float*)d_in[4];
    const float* bv   = (const float*)d_in[5];
    const float* Woff = (const float*)d_in[6];
    const float* boff = (const float*)d_in[7];
    const float* Wa   = (const float*)d_in[8];
    const float* ba   = (const float*)d_in[9];
    const float* Wout = (const float*)d_in[10];
    const float* bout = (const float*)d_in[11];
    float* out = (float*)d_out;

    float *valuep, *offsp, *logitsp, *accp;
    cudaGetSymbolAddress((void**)&valuep,  g_value);
    cudaGetSymbolAddress((void**)&offsp,   g_offs);
    cudaGetSymbolAddress((void**)&logitsp, g_logits);
    cudaGetSymbolAddress((void**)&accp,    g_acc);

    const int M = MROWS;
    const dim3 blk(256);
    const dim3 grid256(DM / 64, (M + 127) / 128);      // N = 256
    const dim3 grid128(128 / 64, (M + 127) / 128);     // N = 128

    // 1. value = input_flatten @ W_value + b_value
    sgemm_bias_kernel<<<grid256, blk>>>(inputf, Wv, bv, valuep, M, DM, DM);
    // 2. offs = query @ W_off + b_off
    sgemm_bias_kernel<<<grid256, blk>>>(query, Woff, boff, offsp, M, DM, DM);
    // 3. logits = query @ W_attn + b_attn
    sgemm_bias_kernel<<<grid128, blk>>>(query, Wa, ba, logitsp, M, 128, DM);
    // 4. softmax + bilinear sampling -> acc
    sample_kernel<<<BATCH * LQ, 256>>>(refp);
    // 5. out = acc @ W_out + b_out
    sgemm_bias_kernel<<<grid256, blk>>>(accp, Wout, bout, out, M, DM, DM);
}

// round 2
// speedup vs baseline: 1.0439x; 1.0439x over previous
#include <cuda_runtime.h>
#include <math.h>
#include <stdint.h>

#define BATCH 2
#define LQ 13294
#define LEN_IN 13294
#define DM 256
#define NH 8
#define HD 32
#define MROWS (BATCH * LQ)   // 26588

// ---------------- scratch (device globals; no allocations allowed) ----------
__device__ float g_value[(size_t)BATCH * LEN_IN * DM];   // [B, LEN_IN, NH, HD]
__device__ float g_offs[(size_t)BATCH * LQ * DM];        // [B, LQ, NH, 16, 2]
__device__ float g_logits[(size_t)BATCH * LQ * NH * 16]; // [B, LQ, NH, 16]
__device__ float g_acc[(size_t)BATCH * LQ * DM];         // [B, LQ, NH, HD]

// ---------------- SGEMM: C[M,N] = A[M,K] @ B[K,N] + bias[N] -----------------
// BM=128, BN=128, BK=16, TM=8, TN=8, 256 threads, double-buffered smem.
__global__ __launch_bounds__(256) void sgemm_bias_kernel(
    const float* __restrict__ A, const float* __restrict__ B,
    const float* __restrict__ bias, float* __restrict__ C,
    int M, int N, int K)
{
    constexpr int BM = 128, BN = 128, BK = 16, TM = 8, TN = 8;
    __shared__ __align__(16) float As[2][BK][BM];   // transposed A tile
    __shared__ __align__(16) float Bs[2][BK][BN];

    const int tid = threadIdx.x;
    const int tx = tid & 15;   // N dir: 16 * 8 = 128
    const int ty = tid >> 4;   // M dir: 16 * 8 = 128
    const int bm = blockIdx.y * BM;
    const int bn = blockIdx.x * BN;

    // A tile: 128 rows x 16 cols = 512 float4, 2 per thread
    const int arow  = tid >> 2;        // 0..63 (+64 second pass)
    const int acol4 = (tid & 3) * 4;   // 0,4,8,12
    // B tile: 16 rows x 128 cols = 512 float4, 2 per thread
    const int brow = tid >> 5;         // 0..7 (+8 second pass)
    const int bcol = (tid & 31) * 4;

    const int nch = K / BK;
    float4 pa[2], pb[2];

    // prefetch chunk 0 into regs
    {
        #pragma unroll
        for (int r = 0; r < 2; ++r) {
            const int row = bm + arow + r * 64;
            pa[r] = make_float4(0.f, 0.f, 0.f, 0.f);
            if (row < M)
                pa[r] = *reinterpret_cast<const float4*>(A + (size_t)row * K + acol4);
            pb[r] = *reinterpret_cast<const float4*>(B + (size_t)(brow + r * 8) * N + bn + bcol);
        }
    }

    float acc[TM][TN] = {};

    for (int chunk = 0; chunk < nch; ++chunk) {
        const int cur = chunk & 1;
        // store prefetched regs into current buffer
        #pragma unroll
        for (int r = 0; r < 2; ++r) {
            As[cur][acol4 + 0][arow + r * 64] = pa[r].x;
            As[cur][acol4 + 1][arow + r * 64] = pa[r].y;
            As[cur][acol4 + 2][arow + r * 64] = pa[r].z;
            As[cur][acol4 + 3][arow + r * 64] = pa[r].w;
            *reinterpret_cast<float4*>(&Bs[cur][brow + r * 8][bcol]) = pb[r];
        }
        __syncthreads();

        // prefetch next chunk
        if (chunk + 1 < nch) {
            const int k0 = (chunk + 1) * BK;
            #pragma unroll
            for (int r = 0; r < 2; ++r) {
                const int row = bm + arow + r * 64;
                pa[r] = make_float4(0.f, 0.f, 0.f, 0.f);
                if (row < M)
                    pa[r] = *reinterpret_cast<const float4*>(A + (size_t)row * K + k0 + acol4);
                pb[r] = *reinterpret_cast<const float4*>(B + (size_t)(k0 + brow + r * 8) * N + bn + bcol);
            }
        }

        #pragma unroll
        for (int k = 0; k < BK; ++k) {
            float4 a0 = *reinterpret_cast<const float4*>(&As[cur][k][ty * TM]);
            float4 a1 = *reinterpret_cast<const float4*>(&As[cur][k][ty * TM + 4]);
            float4 b0 = *reinterpret_cast<const float4*>(&Bs[cur][k][tx * TN]);
            float4 b1 = *reinterpret_cast<const float4*>(&Bs[cur][k][tx * TN + 4]);
            float ra[TM] = {a0.x, a0.y, a0.z, a0.w, a1.x, a1.y, a1.z, a1.w};
            float rb[TN] = {b0.x, b0.y, b0.z, b0.w, b1.x, b1.y, b1.z, b1.w};
            #pragma unroll
            for (int i = 0; i < TM; ++i)
                #pragma unroll
                for (int j = 0; j < TN; ++j)
                    acc[i][j] += ra[i] * rb[j];
        }
        __syncthreads();
    }

    #pragma unroll
    for (int i = 0; i < TM; ++i) {
        const int row = bm + ty * TM + i;
        if (row >= M) continue;
        float* crow = C + (size_t)row * N + bn + tx * TN;
        #pragma unroll
        for (int j = 0; j < TN; j += 4) {
            float4 v;
            v.x = acc[i][j + 0] + bias[bn + tx * TN + j + 0];
            v.y = acc[i][j + 1] + bias[bn + tx * TN + j + 1];
            v.z = acc[i][j + 2] + bias[bn + tx * TN + j + 2];
            v.w = acc[i][j + 3] + bias[bn + tx * TN + j + 3];
            *reinterpret_cast<float4*>(crow + j) = v;
        }
    }
}

// ---------------- sampling + fused 16-way softmax ---------------------------
// One block per (b,q); one warp per head; lane = head-dim channel.
// Lanes 0..15 precompute {4 weights, 4 clamped token ids} per point into smem;
// the gather loop is pure 32-bit IMAD + LDG + FFMA.
__global__ __launch_bounds__(256) void sample_kernel(
    const float* __restrict__ refp)   // [B, LQ, 4, 2]
{
    __shared__ __align__(16) float sw[NH][16][4];  // corner weights (incl. attn wt)
    __shared__ __align__(16) int   si[NH][16][4];  // clamped token indices

    const int bq = blockIdx.x;              // 0 .. B*LQ-1
    const int b  = (bq >= LQ) ? 1 : 0;
    const int h  = threadIdx.x >> 5;
    const int lane = threadIdx.x & 31;

    // ---- softmax over the 16 (level,point) logits (lanes 0..15 hold them) ----
    float logit = -INFINITY;
    if (lane < 16) logit = g_logits[((unsigned)bq * NH + h) * 16 + lane];
    float m = logit;
    #pragma unroll
    for (int o = 16; o > 0; o >>= 1) m = fmaxf(m, __shfl_xor_sync(0xffffffffu, m, o));
    float e = (lane < 16) ? __expf(logit - m) : 0.f;
    float s = e;
    #pragma unroll
    for (int o = 16; o > 0; o >>= 1) s += __shfl_xor_sync(0xffffffffu, s, o);
    const float wt = e / s;

    if (lane < 16) {
        const int LH[4] = {100, 50, 25, 13};
        const int LS[4] = {0, 10000, 12500, 13125};
        const int l = lane >> 2;
        const int w = LH[l], hh = LH[l], s0 = LS[l];
        const float lw = (float)w, lh = (float)hh;

        const float2 off = *reinterpret_cast<const float2*>(
            g_offs + (((unsigned)bq * NH + h) * 16 + lane) * 2);
        const float2 rp = *reinterpret_cast<const float2*>(refp + (unsigned)bq * 8 + l * 2);

        const float x = (rp.x + off.x / lw) * lw - 0.5f;
        const float y = (rp.y + off.y / lh) * lh - 0.5f;
        const float fx = floorf(x), fy = floorf(y);
        const float tx = x - fx, ty = y - fy;
        const int jx = (int)fx, jy = (int)fy;

        const bool xv0 = (jx >= 0) && (jx < w);
        const bool xv1 = (jx + 1 >= 0) && (jx + 1 < w);
        const bool yv0 = (jy >= 0) && (jy < hh);
        const bool yv1 = (jy + 1 >= 0) && (jy + 1 < hh);

        const int cx0 = min(max(jx, 0), w - 1);
        const int cx1 = min(max(jx + 1, 0), w - 1);
        const int cy0 = min(max(jy, 0), hh - 1);
        const int cy1 = min(max(jy + 1, 0), hh - 1);

        const float wx1 = tx, wx0 = 1.f - tx;
        const float wy1 = ty, wy0 = 1.f - ty;

        sw[h][lane][0] = (xv0 && yv0) ? wt * wx0 * wy0 : 0.f;
        sw[h][lane][1] = (xv1 && yv0) ? wt * wx1 * wy0 : 0.f;
        sw[h][lane][2] = (xv0 && yv1) ? wt * wx0 * wy1 : 0.f;
        sw[h][lane][3] = (xv1 && yv1) ? wt * wx1 * wy1 : 0.f;

        si[h][lane][0] = s0 + cy0 * w + cx0;
        si[h][lane][1] = s0 + cy0 * w + cx1;
        si[h][lane][2] = s0 + cy1 * w + cx0;
        si[h][lane][3] = s0 + cy1 * w + cx1;
    }
    __syncwarp();

    // gather: all 32-bit indexing, coalesced 128B per corner
    const float* __restrict__ vb =
        g_value + ((unsigned)b * LEN_IN) * DM + h * HD + lane;

    float acc0 = 0.f, acc1 = 0.f;
    #pragma unroll
    for (int i = 0; i < 16; ++i) {
        const float4 wv = *reinterpret_cast<const float4*>(sw[h][i]);
        const int4   iv = *reinterpret_cast<const int4*>(si[h][i]);
        acc0 += wv.x * __ldg(vb + (unsigned)iv.x * DM);
        acc1 += wv.y * __ldg(vb + (unsigned)iv.y * DM);
        acc0 += wv.z * __ldg(vb + (unsigned)iv.z * DM);
        acc1 += wv.w * __ldg(vb + (unsigned)iv.w * DM);
    }
    g_acc[(unsigned)bq * DM + h * HD + lane] = acc0 + acc1;
}

// ---------------- launch ----------------------------------------------------
extern "C" void kernel_launch(void* const* d_in, const int* in_sizes, int n_in,
                              void* d_out, int out_size)
{
    const float* query  = (const float*)d_in[0];
    const float* refp   = (const float*)d_in[1];
    const float* inputf = (const float*)d_in[2];
    // d_in[3] = input_spatial_shapes (compile-time constants)
    const float* Wv   = (const float*)d_in[4];
    const float* bv   = (const float*)d_in[5];
    const float* Woff = (const float*)d_in[6];
    const float* boff = (const float*)d_in[7];
    const float* Wa   = (const float*)d_in[8];
    const float* ba   = (const float*)d_in[9];
    const float* Wout = (const float*)d_in[10];
    const float* bout = (const float*)d_in[11];
    float* out = (float*)d_out;

    float *valuep, *offsp, *logitsp, *accp;
    cudaGetSymbolAddress((void**)&valuep,  g_value);
    cudaGetSymbolAddress((void**)&offsp,   g_offs);
    cudaGetSymbolAddress((void**)&logitsp, g_logits);
    cudaGetSymbolAddress((void**)&accp,    g_acc);

    const int M = MROWS;
    const dim3 blk(256);
    const dim3 grid256(DM / 128, (M + 127) / 128);     // N = 256
    const dim3 grid128(1, (M + 127) / 128);            // N = 128

    // 1. value = input_flatten @ W_value + b_value
    sgemm_bias_kernel<<<grid256, blk>>>(inputf, Wv, bv, valuep, M, DM, DM);
    // 2. offs = query @ W_off + b_off
    sgemm_bias_kernel<<<grid256, blk>>>(query, Woff, boff, offsp, M, DM, DM);
    // 3. logits = query @ W_attn + b_attn
    sgemm_bias_kernel<<<grid128, blk>>>(query, Wa, ba, logitsp, M, 128, DM);
    // 4. softmax + bilinear sampling -> acc
    sample_kernel<<<BATCH * LQ, 256>>>(refp);
    // 5. out = acc @ W_out + b_out
    sgemm_bias_kernel<<<grid256, blk>>>(accp, Wout, bout, out, M, DM, DM);
}